// round 14
// baseline (speedup 1.0000x reference)
#include <cuda_runtime.h>
#include <cuda_bf16.h>
#include <cstdint>

#define N_NODES    65536
#define N_EDGES    524288
#define HID        128
#define NUM_GRAPHS 128
#define NPG        512
#define K_POOL     256
#define OUT_DIM    10
#define CAP        128        // neighbor slots per node (dataset max deg ~25)

// ---------------- scratch (device globals; no allocation allowed) ----------
__device__ __align__(16) float g_h [N_NODES * HID];   // 32 MB
__device__ __align__(16) float g_hw[N_NODES * HID];   // 32 MB
__device__ int   g_cnt [N_NODES];
__device__ int   g_col2[(size_t)N_NODES * CAP];       // 32 MB slot table
__device__ float g_score[N_NODES];
__device__ __align__(16) float g_pooled[NUM_GRAPHS * HID];
__device__ int   g_is64;
// prepped weights: 4 matrices, bf16 hi/lo, plain k-major [k=128][n=128]
__device__ __align__(16) __nv_bfloat16 g_Whi[4 * 16384];
__device__ __align__(16) __nv_bfloat16 g_Wlo[4 * 16384];

// ---------------- helpers ----------------------------------------------------
__device__ __forceinline__ uint32_t smem_u32(const void* p) {
    uint32_t a;
    asm("{ .reg .u64 t; cvta.to.shared.u64 t, %1; cvt.u32.u64 %0, t; }" : "=r"(a) : "l"(p));
    return a;
}
__device__ __forceinline__ void ldsm_x4(uint32_t* r, uint32_t addr) {
    asm volatile("ldmatrix.sync.aligned.m8n8.x4.shared.b16 {%0,%1,%2,%3}, [%4];"
                 : "=r"(r[0]), "=r"(r[1]), "=r"(r[2]), "=r"(r[3]) : "r"(addr));
}
__device__ __forceinline__ void ldsm_x4_t(uint32_t* r, uint32_t addr) {
    asm volatile("ldmatrix.sync.aligned.m8n8.x4.trans.shared.b16 {%0,%1,%2,%3}, [%4];"
                 : "=r"(r[0]), "=r"(r[1]), "=r"(r[2]), "=r"(r[3]) : "r"(addr));
}
__device__ __forceinline__ void mma_bf16(float* d, const uint32_t* a, const uint32_t* b) {
    asm volatile(
        "mma.sync.aligned.m16n8k16.row.col.f32.bf16.bf16.f32 "
        "{%0,%1,%2,%3}, {%4,%5,%6,%7}, {%8,%9}, {%0,%1,%2,%3};"
        : "+f"(d[0]), "+f"(d[1]), "+f"(d[2]), "+f"(d[3])
        : "r"(a[0]), "r"(a[1]), "r"(a[2]), "r"(a[3]), "r"(b[0]), "r"(b[1]));
}

__device__ __forceinline__ int edge_val(const int* __restrict__ e32, int idx) {
    return g_is64 ? e32[2 * idx] : e32[idx];
}

// ---------------- zero counters + edge dtype detect --------------------------
__global__ void k_zero(const int* __restrict__ e32) {
    int i = blockIdx.x * 1024 + threadIdx.x;
    g_cnt[i] = 0;
    if (blockIdx.x == 0 && threadIdx.x < 32) {
        // int64 ids < 65536 -> high words all zero; int32 data has ids there
        int nz = 0;
#pragma unroll
        for (int j = 0; j < 4; j++) nz |= e32[2 * (threadIdx.x * 4 + j) + 1];
        unsigned any = __ballot_sync(0xffffffffu, nz != 0);
        if (threadIdx.x == 0) g_is64 = (any == 0u) ? 1 : 0;
    }
}

// ---------------- fused build: slot-fill edges + bf16 weight split ----------
__global__ __launch_bounds__(256)
void k_build(const int* __restrict__ e32,
             const float* __restrict__ embW, const float* __restrict__ gcnW)
{
    int b = blockIdx.x;
    if (b < N_EDGES / 256) {
        int e = b * 256 + threadIdx.x;
        int d = edge_val(e32, N_EDGES + e);
        int s = edge_val(e32, e);
        int p = atomicAdd(&g_cnt[d], 1);
        if (p < CAP) g_col2[(size_t)d * CAP + p] = s;
    } else {
        int wm = b - N_EDGES / 256;   // 0 = emb, 1..3 = gcn layers
        const float* W = (wm == 0) ? embW : (gcnW + (wm - 1) * HID * HID);
        __nv_bfloat16* dhi = g_Whi + wm * 16384;
        __nv_bfloat16* dlo = g_Wlo + wm * 16384;
        for (int i = threadIdx.x; i < 16384; i += 256) {
            float v = W[i];
            __nv_bfloat16 hi = __float2bfloat16(v);
            __nv_bfloat16 lo = __float2bfloat16(v - __bfloat162float(hi));
            dhi[i] = hi;
            dlo[i] = lo;
        }
    }
}

// ---------------- tensor-core GEMM via mma.sync (split-bf16, 3 passes) ------
// out[M,128] = A[M,128] @ W[128,128] (+bias). 128 rows/CTA, 8 warps,
// warp tile 32x64, fp32 reg accum. SMEM: A-hi, A-lo, one W buffer
// (time-multiplexed hi -> lo) = 104 KB -> 2 CTAs/SM.
#define SMSTRIDE 136
#define TILE_B   (128 * SMSTRIDE * 2)
#define GEMM_SMEM (3 * TILE_B)

__global__ __launch_bounds__(256, 2)
void k_gemm_mma(const float* __restrict__ A, int widx,
                const float* __restrict__ bias, float* __restrict__ out)
{
    extern __shared__ char dsm[];
    __nv_bfloat16* sAhi = (__nv_bfloat16*)dsm;
    __nv_bfloat16* sAlo = sAhi + 128 * SMSTRIDE;
    __nv_bfloat16* sW   = sAlo + 128 * SMSTRIDE;
    __shared__ float s_bias[128];

    const int tid = threadIdx.x;
    const size_t m0 = (size_t)blockIdx.x * 128;

    const uint4* whi = (const uint4*)(g_Whi + widx * 16384);
    const uint4* wlo = (const uint4*)(g_Wlo + widx * 16384);

#pragma unroll
    for (int i = 0; i < 8; i++) {
        int idx = i * 256 + tid;
        int r = idx >> 4, c = idx & 15;
        *(uint4*)(sW + r * SMSTRIDE + c * 8) = whi[idx];
    }
    {
        const float4* A4 = (const float4*)(A + m0 * HID);
#pragma unroll
        for (int i = 0; i < 16; i++) {
            int idx = i * 256 + tid;
            int row = idx >> 5, k = (idx & 31) * 4;
            float4 v = A4[idx];
            __nv_bfloat16 h0 = __float2bfloat16(v.x);
            __nv_bfloat16 h1 = __float2bfloat16(v.y);
            __nv_bfloat16 h2 = __float2bfloat16(v.z);
            __nv_bfloat16 h3 = __float2bfloat16(v.w);
            __nv_bfloat16 l0 = __float2bfloat16(v.x - __bfloat162float(h0));
            __nv_bfloat16 l1 = __float2bfloat16(v.y - __bfloat162float(h1));
            __nv_bfloat16 l2 = __float2bfloat16(v.z - __bfloat162float(h2));
            __nv_bfloat16 l3 = __float2bfloat16(v.w - __bfloat162float(h3));
            __nv_bfloat162 hA = __halves2bfloat162(h0, h1);
            __nv_bfloat162 hB = __halves2bfloat162(h2, h3);
            __nv_bfloat162 lA = __halves2bfloat162(l0, l1);
            __nv_bfloat162 lB = __halves2bfloat162(l2, l3);
            *(uint2*)(sAhi + row * SMSTRIDE + k) = make_uint2(*(uint32_t*)&hA, *(uint32_t*)&hB);
            *(uint2*)(sAlo + row * SMSTRIDE + k) = make_uint2(*(uint32_t*)&lA, *(uint32_t*)&lB);
        }
    }
    if (tid < 128) s_bias[tid] = bias ? bias[tid] : 0.f;
    __syncthreads();

    const int lane = tid & 31, wid = tid >> 5;
    const int m_warp = (wid & 3) * 32;
    const int n_warp = (wid >> 2) * 64;

    float acc[2][8][4];
#pragma unroll
    for (int mt = 0; mt < 2; mt++)
#pragma unroll
        for (int nt = 0; nt < 8; nt++)
#pragma unroll
            for (int i = 0; i < 4; i++) acc[mt][nt][i] = 0.f;

    const uint32_t uAhi = smem_u32(sAhi);
    const uint32_t uAlo = smem_u32(sAlo);
    const uint32_t uW   = smem_u32(sW);

    uint32_t aoff[2], boff[4];
#pragma unroll
    for (int mt = 0; mt < 2; mt++)
        aoff[mt] = ((m_warp + mt * 16 + (lane & 15)) * SMSTRIDE + (lane >> 4) * 8) * 2;
#pragma unroll
    for (int p = 0; p < 4; p++)
        boff[p] = ((((lane >> 3) & 1) * 8 + (lane & 7)) * SMSTRIDE
                   + n_warp + p * 16 + (lane >> 4) * 8) * 2;

    // phase 1: B = W-hi; A-hi and A-lo share B fragments
#pragma unroll
    for (int ks = 0; ks < 8; ks++) {
        uint32_t b[4][4], a[2][4];
#pragma unroll
        for (int p = 0; p < 4; p++)
            ldsm_x4_t(b[p], uW + boff[p] + ks * 16 * SMSTRIDE * 2);
        ldsm_x4(a[0], uAhi + aoff[0] + ks * 32);
        ldsm_x4(a[1], uAhi + aoff[1] + ks * 32);
#pragma unroll
        for (int mt = 0; mt < 2; mt++)
#pragma unroll
            for (int nt = 0; nt < 8; nt++)
                mma_bf16(acc[mt][nt], a[mt], &b[nt >> 1][(nt & 1) * 2]);
        ldsm_x4(a[0], uAlo + aoff[0] + ks * 32);
        ldsm_x4(a[1], uAlo + aoff[1] + ks * 32);
#pragma unroll
        for (int mt = 0; mt < 2; mt++)
#pragma unroll
            for (int nt = 0; nt < 8; nt++)
                mma_bf16(acc[mt][nt], a[mt], &b[nt >> 1][(nt & 1) * 2]);
    }

    __syncthreads();
#pragma unroll
    for (int i = 0; i < 8; i++) {
        int idx = i * 256 + tid;
        int r = idx >> 4, c = idx & 15;
        *(uint4*)(sW + r * SMSTRIDE + c * 8) = wlo[idx];
    }
    __syncthreads();

    // phase 2: A-hi x W-lo
#pragma unroll
    for (int ks = 0; ks < 8; ks++) {
        uint32_t b[4][4], a[2][4];
#pragma unroll
        for (int p = 0; p < 4; p++)
            ldsm_x4_t(b[p], uW + boff[p] + ks * 16 * SMSTRIDE * 2);
        ldsm_x4(a[0], uAhi + aoff[0] + ks * 32);
        ldsm_x4(a[1], uAhi + aoff[1] + ks * 32);
#pragma unroll
        for (int mt = 0; mt < 2; mt++)
#pragma unroll
            for (int nt = 0; nt < 8; nt++)
                mma_bf16(acc[mt][nt], a[mt], &b[nt >> 1][(nt & 1) * 2]);
    }

    const int g4 = lane >> 2, tig = lane & 3;
#pragma unroll
    for (int mt = 0; mt < 2; mt++) {
        size_t r0 = m0 + m_warp + mt * 16 + g4;
#pragma unroll
        for (int nt = 0; nt < 8; nt++) {
            int col = n_warp + nt * 8 + tig * 2;
            float bx = s_bias[col], by = s_bias[col + 1];
            float2 v0 = make_float2(acc[mt][nt][0] + bx, acc[mt][nt][1] + by);
            float2 v1 = make_float2(acc[mt][nt][2] + bx, acc[mt][nt][3] + by);
            *(float2*)(out + r0 * HID + col)       = v0;
            *(float2*)(out + (r0 + 8) * HID + col) = v1;
        }
    }
}

// ---------------- GCN aggregation: warp per destination node ---------------
// Slot-table neighbors; dinv computed from counts on the fly; lane-parallel
// index prefetch + shfl broadcast; optional fused TopK score.
template <bool WITH_SCORE>
__global__ void k_aggregate(const float* __restrict__ hw, const float* __restrict__ bias,
                            float* __restrict__ hout, const float* __restrict__ poolp)
{
    int gw = (blockIdx.x * blockDim.x + threadIdx.x) >> 5;
    if (gw >= N_NODES) return;
    int lane = threadIdx.x & 31;
    int cnt = min(g_cnt[gw], CAP);
    float di = rsqrtf((float)cnt + 1.0f);
    float4 s = ((const float4*)(hw + (size_t)gw * HID))[lane];
    float w0 = di * di;
    float ax = s.x * w0, ay = s.y * w0, az = s.z * w0, aw = s.w * w0;
    const int* row = g_col2 + (size_t)gw * CAP;
    for (int base = 0; base < cnt; base += 32) {
        int n = min(32, cnt - base);
        int   myc = 0;
        float mydv = 0.f;
        if (lane < n) {
            myc  = row[base + lane];
            mydv = rsqrtf((float)min(g_cnt[myc], CAP) + 1.0f);
        }
        for (int j = 0; j < n; j++) {
            int   sn = __shfl_sync(0xffffffffu, myc, j);
            float nv = __shfl_sync(0xffffffffu, mydv, j);
            float nrm = di * nv;
            float4 v = ((const float4*)(hw + (size_t)sn * HID))[lane];
            ax = fmaf(v.x, nrm, ax); ay = fmaf(v.y, nrm, ay);
            az = fmaf(v.z, nrm, az); aw = fmaf(v.w, nrm, aw);
        }
    }
    float4 b = ((const float4*)bias)[lane];
    float4 o;
    o.x = fmaxf(ax + b.x, 0.f); o.y = fmaxf(ay + b.y, 0.f);
    o.z = fmaxf(az + b.z, 0.f); o.w = fmaxf(aw + b.w, 0.f);
    ((float4*)(hout + (size_t)gw * HID))[lane] = o;

    if (WITH_SCORE) {
        float4 p = ((const float4*)poolp)[lane];
        float sacc = o.x * p.x + o.y * p.y + o.z * p.z + o.w * p.w;
        float pn   = p.x * p.x + p.y * p.y + p.z * p.z + p.w * p.w;
#pragma unroll
        for (int off = 16; off; off >>= 1) {
            sacc += __shfl_xor_sync(0xffffffffu, sacc, off);
            pn   += __shfl_xor_sync(0xffffffffu, pn, off);
        }
        if (lane == 0) g_score[gw] = sacc * rsqrtf(pn);
    }
}

// ---------------- TopK pool (ratio .5) + weighted mean ----------------------
__global__ void k_pool(const float* __restrict__ h)
{
    __shared__ float sv[NPG];
    __shared__ int   si[NPG];
    __shared__ float swt[K_POOL];
    __shared__ float red[NPG];
    int g = blockIdx.x, t = threadIdx.x;
    sv[t] = g_score[g * NPG + t];
    si[t] = t;
    __syncthreads();
    for (int k2 = 2; k2 <= NPG; k2 <<= 1) {
        for (int j = k2 >> 1; j > 0; j >>= 1) {
            int ixj = t ^ j;
            if (ixj > t) {
                float va = sv[t], vb = sv[ixj];
                int ia = si[t], ib = si[ixj];
                bool a_first = (va > vb) || (va == vb && ia < ib);
                bool up = ((t & k2) == 0);
                if (up ? !a_first : a_first) {
                    sv[t] = vb; sv[ixj] = va;
                    si[t] = ib; si[ixj] = ia;
                }
            }
            __syncthreads();
        }
    }
    if (t < K_POOL) swt[t] = tanhf(sv[t]) * (1.0f / K_POOL);
    __syncthreads();
    int f = t & 127, part = t >> 7;
    float acc = 0.f;
    const float* hg = h + (size_t)g * NPG * HID;
    for (int j = part * 64; j < part * 64 + 64; j++)
        acc = fmaf(swt[j], hg[(size_t)si[j] * HID + f], acc);
    red[t] = acc;
    __syncthreads();
    if (part == 0)
        g_pooled[g * HID + f] = red[f] + red[128 + f] + red[256 + f] + red[384 + f];
}

// ---------------- MLP head: one block per graph ------------------------------
__global__ void k_mlp(const float* __restrict__ fc1W, const float* __restrict__ fc1b,
                      const float* __restrict__ fc2W, const float* __restrict__ fc2b,
                      const float* __restrict__ fc3W, const float* __restrict__ fc3b,
                      float* __restrict__ out)
{
    __shared__ float sp[128], sz1[128], sz2[64];
    int g = blockIdx.x, t = threadIdx.x;
    sp[t] = g_pooled[g * 128 + t];
    __syncthreads();
    float acc = fc1b[t];
    for (int k = 0; k < 128; k++) acc = fmaf(sp[k], fc1W[k * 128 + t], acc);
    sz1[t] = fmaxf(acc, 0.f);
    __syncthreads();
    if (t < 64) {
        float a2 = fc2b[t];
        for (int k = 0; k < 128; k++) a2 = fmaf(sz1[k], fc2W[k * 64 + t], a2);
        sz2[t] = fmaxf(a2, 0.f);
    }
    __syncthreads();
    if (t < OUT_DIM) {
        float a3 = fc3b[t];
        for (int k = 0; k < 64; k++) a3 = fmaf(sz2[k], fc3W[k * OUT_DIM + t], a3);
        out[g * OUT_DIM + t] = a3;
    }
}

// ---------------- launch -----------------------------------------------------
extern "C" void kernel_launch(void* const* d_in, const int* in_sizes, int n_in,
                              void* d_out, int out_size)
{
    const float* x    = (const float*)d_in[0];
    const int*   ei   = (const int*)d_in[1];
    const float* embW = (const float*)d_in[3];
    const float* embB = (const float*)d_in[4];
    const float* gcnW = (const float*)d_in[5];
    const float* gcnB = (const float*)d_in[6];
    const float* poolP= (const float*)d_in[7];
    const float* fc1W = (const float*)d_in[8];
    const float* fc1b = (const float*)d_in[9];
    const float* fc2W = (const float*)d_in[10];
    const float* fc2b = (const float*)d_in[11];
    const float* fc3W = (const float*)d_in[12];
    const float* fc3b = (const float*)d_in[13];
    float* out = (float*)d_out;

    float *h, *hw;
    cudaGetSymbolAddress((void**)&h,  g_h);
    cudaGetSymbolAddress((void**)&hw, g_hw);

    cudaFuncSetAttribute(k_gemm_mma, cudaFuncAttributeMaxDynamicSharedMemorySize, GEMM_SMEM);

    // graph build: zero+detect, then fused slot-fill + weight split
    k_zero <<<N_NODES / 1024, 1024>>>(ei);
    k_build<<<N_EDGES / 256 + 4, 256>>>(ei, embW, gcnW);

    // embedding
    k_gemm_mma<<<N_NODES / 128, 256, GEMM_SMEM>>>(x, 0, embB, h);

    // 3 GCN layers (score fused into last aggregate)
    k_gemm_mma<<<N_NODES / 128, 256, GEMM_SMEM>>>(h, 1, nullptr, hw);
    k_aggregate<false><<<N_NODES / 8, 256>>>(hw, gcnB + 0 * HID, h, nullptr);
    k_gemm_mma<<<N_NODES / 128, 256, GEMM_SMEM>>>(h, 2, nullptr, hw);
    k_aggregate<false><<<N_NODES / 8, 256>>>(hw, gcnB + 1 * HID, h, nullptr);
    k_gemm_mma<<<N_NODES / 128, 256, GEMM_SMEM>>>(h, 3, nullptr, hw);
    k_aggregate<true><<<N_NODES / 8, 256>>>(hw, gcnB + 2 * HID, h, poolP);

    // pooling + head
    k_pool<<<NUM_GRAPHS, NPG>>>(h);
    k_mlp<<<NUM_GRAPHS, 128>>>(fc1W, fc1b, fc2W, fc2b, fc3W, fc3b, out);
}

// round 15
// speedup vs baseline: 1.0238x; 1.0238x over previous
#include <cuda_runtime.h>
#include <cuda_bf16.h>
#include <cstdint>

#define N_NODES    65536
#define N_EDGES    524288
#define HID        128
#define NUM_GRAPHS 128
#define NPG        512
#define K_POOL     256
#define OUT_DIM    10
#define CAP        128        // neighbor slots per node (dataset max deg ~25)

// ---------------- scratch (device globals; no allocation allowed) ----------
__device__ __align__(16) float g_h [N_NODES * HID];   // 32 MB
__device__ __align__(16) float g_hw[N_NODES * HID];   // 32 MB
__device__ int   g_cnt [N_NODES];
__device__ int   g_col2[(size_t)N_NODES * CAP];       // 32 MB slot table
__device__ float g_score[N_NODES];
__device__ __align__(16) float g_pooled[NUM_GRAPHS * HID];
__device__ int   g_is64;
// prepped weights: 4 matrices, bf16 hi/lo, plain k-major [k=128][n=128]
__device__ __align__(16) __nv_bfloat16 g_Whi[4 * 16384];
__device__ __align__(16) __nv_bfloat16 g_Wlo[4 * 16384];

// ---------------- helpers ----------------------------------------------------
__device__ __forceinline__ uint32_t smem_u32(const void* p) {
    uint32_t a;
    asm("{ .reg .u64 t; cvta.to.shared.u64 t, %1; cvt.u32.u64 %0, t; }" : "=r"(a) : "l"(p));
    return a;
}
__device__ __forceinline__ void ldsm_x4(uint32_t* r, uint32_t addr) {
    asm volatile("ldmatrix.sync.aligned.m8n8.x4.shared.b16 {%0,%1,%2,%3}, [%4];"
                 : "=r"(r[0]), "=r"(r[1]), "=r"(r[2]), "=r"(r[3]) : "r"(addr));
}
__device__ __forceinline__ void ldsm_x4_t(uint32_t* r, uint32_t addr) {
    asm volatile("ldmatrix.sync.aligned.m8n8.x4.trans.shared.b16 {%0,%1,%2,%3}, [%4];"
                 : "=r"(r[0]), "=r"(r[1]), "=r"(r[2]), "=r"(r[3]) : "r"(addr));
}
__device__ __forceinline__ void mma_bf16(float* d, const uint32_t* a, const uint32_t* b) {
    asm volatile(
        "mma.sync.aligned.m16n8k16.row.col.f32.bf16.bf16.f32 "
        "{%0,%1,%2,%3}, {%4,%5,%6,%7}, {%8,%9}, {%0,%1,%2,%3};"
        : "+f"(d[0]), "+f"(d[1]), "+f"(d[2]), "+f"(d[3])
        : "r"(a[0]), "r"(a[1]), "r"(a[2]), "r"(a[3]), "r"(b[0]), "r"(b[1]));
}

__device__ __forceinline__ int edge_val(const int* __restrict__ e32, int idx) {
    return g_is64 ? e32[2 * idx] : e32[idx];
}

// ---------------- zero counters + edge dtype detect --------------------------
__global__ void k_zero(const int* __restrict__ e32) {
    int i = blockIdx.x * 1024 + threadIdx.x;
    g_cnt[i] = 0;
    if (blockIdx.x == 0 && threadIdx.x < 32) {
        // int64 ids < 65536 -> high words all zero; int32 data has ids there
        int nz = 0;
#pragma unroll
        for (int j = 0; j < 4; j++) nz |= e32[2 * (threadIdx.x * 4 + j) + 1];
        unsigned any = __ballot_sync(0xffffffffu, nz != 0);
        if (threadIdx.x == 0) g_is64 = (any == 0u) ? 1 : 0;
    }
}

// ---------------- fused build: slot-fill edges + bf16 weight split ----------
__global__ __launch_bounds__(256)
void k_build(const int* __restrict__ e32,
             const float* __restrict__ embW, const float* __restrict__ gcnW)
{
    int b = blockIdx.x;
    if (b < N_EDGES / 256) {
        int e = b * 256 + threadIdx.x;
        int d = edge_val(e32, N_EDGES + e);
        int s = edge_val(e32, e);
        int p = atomicAdd(&g_cnt[d], 1);
        if (p < CAP) g_col2[(size_t)d * CAP + p] = s;
    } else {
        int wm = b - N_EDGES / 256;   // 0 = emb, 1..3 = gcn layers
        const float* W = (wm == 0) ? embW : (gcnW + (wm - 1) * HID * HID);
        __nv_bfloat16* dhi = g_Whi + wm * 16384;
        __nv_bfloat16* dlo = g_Wlo + wm * 16384;
        for (int i = threadIdx.x; i < 16384; i += 256) {
            float v = W[i];
            __nv_bfloat16 hi = __float2bfloat16(v);
            __nv_bfloat16 lo = __float2bfloat16(v - __bfloat162float(hi));
            dhi[i] = hi;
            dlo[i] = lo;
        }
    }
}

// ---------------- tensor-core GEMM via mma.sync (split-bf16, 3 passes) ------
// out[M,128] = A[M,128] @ W[128,128] (+bias). 128 rows/CTA, 8 warps,
// warp tile 32x64, fp32 reg accum. SMEM: A-hi, A-lo, one W buffer
// (time-multiplexed hi -> lo) = 104 KB -> 2 CTAs/SM.
#define SMSTRIDE 136
#define TILE_B   (128 * SMSTRIDE * 2)
#define GEMM_SMEM (3 * TILE_B)

__global__ __launch_bounds__(256, 2)
void k_gemm_mma(const float* __restrict__ A, int widx,
                const float* __restrict__ bias, float* __restrict__ out)
{
    extern __shared__ char dsm[];
    __nv_bfloat16* sAhi = (__nv_bfloat16*)dsm;
    __nv_bfloat16* sAlo = sAhi + 128 * SMSTRIDE;
    __nv_bfloat16* sW   = sAlo + 128 * SMSTRIDE;
    __shared__ float s_bias[128];

    const int tid = threadIdx.x;
    const size_t m0 = (size_t)blockIdx.x * 128;

    const uint4* whi = (const uint4*)(g_Whi + widx * 16384);
    const uint4* wlo = (const uint4*)(g_Wlo + widx * 16384);

#pragma unroll
    for (int i = 0; i < 8; i++) {
        int idx = i * 256 + tid;
        int r = idx >> 4, c = idx & 15;
        *(uint4*)(sW + r * SMSTRIDE + c * 8) = whi[idx];
    }
    {
        const float4* A4 = (const float4*)(A + m0 * HID);
#pragma unroll
        for (int i = 0; i < 16; i++) {
            int idx = i * 256 + tid;
            int row = idx >> 5, k = (idx & 31) * 4;
            float4 v = A4[idx];
            __nv_bfloat16 h0 = __float2bfloat16(v.x);
            __nv_bfloat16 h1 = __float2bfloat16(v.y);
            __nv_bfloat16 h2 = __float2bfloat16(v.z);
            __nv_bfloat16 h3 = __float2bfloat16(v.w);
            __nv_bfloat16 l0 = __float2bfloat16(v.x - __bfloat162float(h0));
            __nv_bfloat16 l1 = __float2bfloat16(v.y - __bfloat162float(h1));
            __nv_bfloat16 l2 = __float2bfloat16(v.z - __bfloat162float(h2));
            __nv_bfloat16 l3 = __float2bfloat16(v.w - __bfloat162float(h3));
            __nv_bfloat162 hA = __halves2bfloat162(h0, h1);
            __nv_bfloat162 hB = __halves2bfloat162(h2, h3);
            __nv_bfloat162 lA = __halves2bfloat162(l0, l1);
            __nv_bfloat162 lB = __halves2bfloat162(l2, l3);
            *(uint2*)(sAhi + row * SMSTRIDE + k) = make_uint2(*(uint32_t*)&hA, *(uint32_t*)&hB);
            *(uint2*)(sAlo + row * SMSTRIDE + k) = make_uint2(*(uint32_t*)&lA, *(uint32_t*)&lB);
        }
    }
    if (tid < 128) s_bias[tid] = bias ? bias[tid] : 0.f;
    __syncthreads();

    const int lane = tid & 31, wid = tid >> 5;
    const int m_warp = (wid & 3) * 32;
    const int n_warp = (wid >> 2) * 64;

    float acc[2][8][4];
#pragma unroll
    for (int mt = 0; mt < 2; mt++)
#pragma unroll
        for (int nt = 0; nt < 8; nt++)
#pragma unroll
            for (int i = 0; i < 4; i++) acc[mt][nt][i] = 0.f;

    const uint32_t uAhi = smem_u32(sAhi);
    const uint32_t uAlo = smem_u32(sAlo);
    const uint32_t uW   = smem_u32(sW);

    uint32_t aoff[2], boff[4];
#pragma unroll
    for (int mt = 0; mt < 2; mt++)
        aoff[mt] = ((m_warp + mt * 16 + (lane & 15)) * SMSTRIDE + (lane >> 4) * 8) * 2;
#pragma unroll
    for (int p = 0; p < 4; p++)
        boff[p] = ((((lane >> 3) & 1) * 8 + (lane & 7)) * SMSTRIDE
                   + n_warp + p * 16 + (lane >> 4) * 8) * 2;

    // phase 1: B = W-hi; A-hi and A-lo share B fragments
#pragma unroll
    for (int ks = 0; ks < 8; ks++) {
        uint32_t b[4][4], a[2][4];
#pragma unroll
        for (int p = 0; p < 4; p++)
            ldsm_x4_t(b[p], uW + boff[p] + ks * 16 * SMSTRIDE * 2);
        ldsm_x4(a[0], uAhi + aoff[0] + ks * 32);
        ldsm_x4(a[1], uAhi + aoff[1] + ks * 32);
#pragma unroll
        for (int mt = 0; mt < 2; mt++)
#pragma unroll
            for (int nt = 0; nt < 8; nt++)
                mma_bf16(acc[mt][nt], a[mt], &b[nt >> 1][(nt & 1) * 2]);
        ldsm_x4(a[0], uAlo + aoff[0] + ks * 32);
        ldsm_x4(a[1], uAlo + aoff[1] + ks * 32);
#pragma unroll
        for (int mt = 0; mt < 2; mt++)
#pragma unroll
            for (int nt = 0; nt < 8; nt++)
                mma_bf16(acc[mt][nt], a[mt], &b[nt >> 1][(nt & 1) * 2]);
    }

    __syncthreads();
#pragma unroll
    for (int i = 0; i < 8; i++) {
        int idx = i * 256 + tid;
        int r = idx >> 4, c = idx & 15;
        *(uint4*)(sW + r * SMSTRIDE + c * 8) = wlo[idx];
    }
    __syncthreads();

    // phase 2: A-hi x W-lo
#pragma unroll
    for (int ks = 0; ks < 8; ks++) {
        uint32_t b[4][4], a[2][4];
#pragma unroll
        for (int p = 0; p < 4; p++)
            ldsm_x4_t(b[p], uW + boff[p] + ks * 16 * SMSTRIDE * 2);
        ldsm_x4(a[0], uAhi + aoff[0] + ks * 32);
        ldsm_x4(a[1], uAhi + aoff[1] + ks * 32);
#pragma unroll
        for (int mt = 0; mt < 2; mt++)
#pragma unroll
            for (int nt = 0; nt < 8; nt++)
                mma_bf16(acc[mt][nt], a[mt], &b[nt >> 1][(nt & 1) * 2]);
    }

    const int g4 = lane >> 2, tig = lane & 3;
#pragma unroll
    for (int mt = 0; mt < 2; mt++) {
        size_t r0 = m0 + m_warp + mt * 16 + g4;
#pragma unroll
        for (int nt = 0; nt < 8; nt++) {
            int col = n_warp + nt * 8 + tig * 2;
            float bx = s_bias[col], by = s_bias[col + 1];
            float2 v0 = make_float2(acc[mt][nt][0] + bx, acc[mt][nt][1] + by);
            float2 v1 = make_float2(acc[mt][nt][2] + bx, acc[mt][nt][3] + by);
            *(float2*)(out + r0 * HID + col)       = v0;
            *(float2*)(out + (r0 + 8) * HID + col) = v1;
        }
    }
}

// ---------------- GCN aggregation: warp per destination node ---------------
// Slot-table neighbors; dinv computed from counts on the fly; lane-parallel
// index prefetch + shfl broadcast; optional fused TopK score.
template <bool WITH_SCORE>
__global__ void k_aggregate(const float* __restrict__ hw, const float* __restrict__ bias,
                            float* __restrict__ hout, const float* __restrict__ poolp)
{
    int gw = (blockIdx.x * blockDim.x + threadIdx.x) >> 5;
    if (gw >= N_NODES) return;
    int lane = threadIdx.x & 31;
    int cnt = min(g_cnt[gw], CAP);
    float di = rsqrtf((float)cnt + 1.0f);
    float4 s = ((const float4*)(hw + (size_t)gw * HID))[lane];
    float w0 = di * di;
    float ax = s.x * w0, ay = s.y * w0, az = s.z * w0, aw = s.w * w0;
    const int* row = g_col2 + (size_t)gw * CAP;
    for (int base = 0; base < cnt; base += 32) {
        int n = min(32, cnt - base);
        int   myc = 0;
        float mydv = 0.f;
        if (lane < n) {
            myc  = row[base + lane];
            mydv = rsqrtf((float)min(g_cnt[myc], CAP) + 1.0f);
        }
        for (int j = 0; j < n; j++) {
            int   sn = __shfl_sync(0xffffffffu, myc, j);
            float nv = __shfl_sync(0xffffffffu, mydv, j);
            float nrm = di * nv;
            float4 v = ((const float4*)(hw + (size_t)sn * HID))[lane];
            ax = fmaf(v.x, nrm, ax); ay = fmaf(v.y, nrm, ay);
            az = fmaf(v.z, nrm, az); aw = fmaf(v.w, nrm, aw);
        }
    }
    float4 b = ((const float4*)bias)[lane];
    float4 o;
    o.x = fmaxf(ax + b.x, 0.f); o.y = fmaxf(ay + b.y, 0.f);
    o.z = fmaxf(az + b.z, 0.f); o.w = fmaxf(aw + b.w, 0.f);
    ((float4*)(hout + (size_t)gw * HID))[lane] = o;

    if (WITH_SCORE) {
        float4 p = ((const float4*)poolp)[lane];
        float sacc = o.x * p.x + o.y * p.y + o.z * p.z + o.w * p.w;
        float pn   = p.x * p.x + p.y * p.y + p.z * p.z + p.w * p.w;
#pragma unroll
        for (int off = 16; off; off >>= 1) {
            sacc += __shfl_xor_sync(0xffffffffu, sacc, off);
            pn   += __shfl_xor_sync(0xffffffffu, pn, off);
        }
        if (lane == 0) g_score[gw] = sacc * rsqrtf(pn);
    }
}

// ---------------- TopK pool (ratio .5) + weighted mean ----------------------
__global__ void k_pool(const float* __restrict__ h)
{
    __shared__ float sv[NPG];
    __shared__ int   si[NPG];
    __shared__ float swt[K_POOL];
    __shared__ float red[NPG];
    int g = blockIdx.x, t = threadIdx.x;
    sv[t] = g_score[g * NPG + t];
    si[t] = t;
    __syncthreads();
    for (int k2 = 2; k2 <= NPG; k2 <<= 1) {
        for (int j = k2 >> 1; j > 0; j >>= 1) {
            int ixj = t ^ j;
            if (ixj > t) {
                float va = sv[t], vb = sv[ixj];
                int ia = si[t], ib = si[ixj];
                bool a_first = (va > vb) || (va == vb && ia < ib);
                bool up = ((t & k2) == 0);
                if (up ? !a_first : a_first) {
                    sv[t] = vb; sv[ixj] = va;
                    si[t] = ib; si[ixj] = ia;
                }
            }
            __syncthreads();
        }
    }
    if (t < K_POOL) swt[t] = tanhf(sv[t]) * (1.0f / K_POOL);
    __syncthreads();
    int f = t & 127, part = t >> 7;
    float acc = 0.f;
    const float* hg = h + (size_t)g * NPG * HID;
    for (int j = part * 64; j < part * 64 + 64; j++)
        acc = fmaf(swt[j], hg[(size_t)si[j] * HID + f], acc);
    red[t] = acc;
    __syncthreads();
    if (part == 0)
        g_pooled[g * HID + f] = red[f] + red[128 + f] + red[256 + f] + red[384 + f];
}

// ---------------- MLP head: one block per graph ------------------------------
__global__ void k_mlp(const float* __restrict__ fc1W, const float* __restrict__ fc1b,
                      const float* __restrict__ fc2W, const float* __restrict__ fc2b,
                      const float* __restrict__ fc3W, const float* __restrict__ fc3b,
                      float* __restrict__ out)
{
    __shared__ float sp[128], sz1[128], sz2[64];
    int g = blockIdx.x, t = threadIdx.x;
    sp[t] = g_pooled[g * 128 + t];
    __syncthreads();
    float acc = fc1b[t];
    for (int k = 0; k < 128; k++) acc = fmaf(sp[k], fc1W[k * 128 + t], acc);
    sz1[t] = fmaxf(acc, 0.f);
    __syncthreads();
    if (t < 64) {
        float a2 = fc2b[t];
        for (int k = 0; k < 128; k++) a2 = fmaf(sz1[k], fc2W[k * 64 + t], a2);
        sz2[t] = fmaxf(a2, 0.f);
    }
    __syncthreads();
    if (t < OUT_DIM) {
        float a3 = fc3b[t];
        for (int k = 0; k < 64; k++) a3 = fmaf(sz2[k], fc3W[k * OUT_DIM + t], a3);
        out[g * OUT_DIM + t] = a3;
    }
}

// ---------------- launch -----------------------------------------------------
extern "C" void kernel_launch(void* const* d_in, const int* in_sizes, int n_in,
                              void* d_out, int out_size)
{
    const float* x    = (const float*)d_in[0];
    const int*   ei   = (const int*)d_in[1];
    const float* embW = (const float*)d_in[3];
    const float* embB = (const float*)d_in[4];
    const float* gcnW = (const float*)d_in[5];
    const float* gcnB = (const float*)d_in[6];
    const float* poolP= (const float*)d_in[7];
    const float* fc1W = (const float*)d_in[8];
    const float* fc1b = (const float*)d_in[9];
    const float* fc2W = (const float*)d_in[10];
    const float* fc2b = (const float*)d_in[11];
    const float* fc3W = (const float*)d_in[12];
    const float* fc3b = (const float*)d_in[13];
    float* out = (float*)d_out;

    float *h, *hw;
    cudaGetSymbolAddress((void**)&h,  g_h);
    cudaGetSymbolAddress((void**)&hw, g_hw);

    cudaFuncSetAttribute(k_gemm_mma, cudaFuncAttributeMaxDynamicSharedMemorySize, GEMM_SMEM);

    // graph build: zero+detect, then fused slot-fill + weight split
    k_zero <<<N_NODES / 1024, 1024>>>(ei);
    k_build<<<N_EDGES / 256 + 4, 256>>>(ei, embW, gcnW);

    // embedding
    k_gemm_mma<<<N_NODES / 128, 256, GEMM_SMEM>>>(x, 0, embB, h);

    // 3 GCN layers (score fused into last aggregate)
    k_gemm_mma<<<N_NODES / 128, 256, GEMM_SMEM>>>(h, 1, nullptr, hw);
    k_aggregate<false><<<N_NODES / 8, 256>>>(hw, gcnB + 0 * HID, h, nullptr);
    k_gemm_mma<<<N_NODES / 128, 256, GEMM_SMEM>>>(h, 2, nullptr, hw);
    k_aggregate<false><<<N_NODES / 8, 256>>>(hw, gcnB + 1 * HID, h, nullptr);
    k_gemm_mma<<<N_NODES / 128, 256, GEMM_SMEM>>>(h, 3, nullptr, hw);
    k_aggregate<true><<<N_NODES / 8, 256>>>(hw, gcnB + 2 * HID, h, poolP);

    // pooling + head
    k_pool<<<NUM_GRAPHS, NPG>>>(h);
    k_mlp<<<NUM_GRAPHS, 128>>>(fc1W, fc1b, fc2W, fc2b, fc3W, fc3b, out);
}